// round 12
// baseline (speedup 1.0000x reference)
#include <cuda_runtime.h>
#include <cuda_fp16.h>
#include <cstdint>

#define NN   100000
#define DD   64
#define INV  128
#define NC   40
#define NE   1600000
#define NLAY 4
#define NSB  391         // offset blocks: ceil(NN/256)
#define SWH  72          // smem stride in halves (144B = 4 banks mod 32)
#define SWI  136         // input gemm stride in halves (272B = 4 banks mod 32)
#define GRID 444         // persistent kernel grid: 148 SMs x 3 CTAs (guaranteed resident)
#define NTILE 1563       // ceil(NN/64)

// ---- scratch (device globals: no allocations allowed) ----
__device__ __align__(128) float  g_h[NN * DD];
__device__ __align__(128) __half g_hs16[NN * DD];   // (h * norm_src) in fp16
__device__ __align__(128) __half g_agg16[NN * DD];  // gathered agg in fp16
__device__ __align__(128) __half g_hc16[NN * DD];   // conv output in fp16
__device__ float g_norm_src[NN];
__device__ float g_norm_dst[NN];
__device__ int   g_deg_out[NN];
__device__ int   g_row_ptr[NN];
__device__ int   g_row_end[NN];
__device__ int   g_cursor[NN];
__device__ int   g_col[NE];
__device__ int   g_total;
__device__ unsigned g_bar;                 // persistent-kernel barrier counter
__device__ float g_stats[NLAY * 2 * DD];   // per-layer slots

// ---------------------------------------------------------------------------
__device__ __forceinline__ void mma_f16(
        float& c0, float& c1, float& c2, float& c3,
        uint32_t a0, uint32_t a1, uint32_t a2, uint32_t a3,
        uint32_t b0, uint32_t b1) {
    asm volatile(
        "mma.sync.aligned.m16n8k16.row.col.f32.f16.f16.f32 "
        "{%0,%1,%2,%3}, {%4,%5,%6,%7}, {%8,%9}, {%0,%1,%2,%3};"
        : "+f"(c0), "+f"(c1), "+f"(c2), "+f"(c3)
        : "r"(a0), "r"(a1), "r"(a2), "r"(a3), "r"(b0), "r"(b1));
}

// grid-wide soft barrier; all GRID blocks are co-resident by construction.
__device__ __forceinline__ void grid_bar(unsigned target) {
    __syncthreads();
    if (threadIdx.x == 0) {
        __threadfence();                       // release
        atomicAdd(&g_bar, 1u);
        unsigned v;
        do {
            asm volatile("ld.acquire.gpu.u32 %0, [%1];"
                         : "=r"(v) : "l"(&g_bar) : "memory");
        } while (v < target);
        __threadfence();                       // acquire + L1 invalidate
    }
    __syncthreads();
}

// ---------------------------------------------------------------------------
__global__ void init_kernel() {
    int i = blockIdx.x * 256 + threadIdx.x;
    if (i < NN) { g_deg_out[i] = 0; g_cursor[i] = 0; }
    if (i < NLAY * 2 * DD) g_stats[i] = 0.f;
    if (i == 0) { g_total = 0; g_bar = 0u; }
}

__global__ void deg_kernel(const int* __restrict__ src, const int* __restrict__ dst) {
    int i = blockIdx.x * 256 + threadIdx.x;
    if (i < NE) {
        atomicAdd(&g_deg_out[src[i]], 1);
        atomicAdd(&g_cursor[dst[i]], 1);     // g_cursor = in-degree (temp)
    }
}

__global__ void offsets_kernel() {
    __shared__ int s[256];
    __shared__ int base;
    int t = threadIdx.x;
    int i = blockIdx.x * 256 + t;
    int d = (i < NN) ? g_cursor[i] : 0;
    s[t] = d;
    __syncthreads();
    for (int off = 1; off < 256; off <<= 1) {
        int v = (t >= off) ? s[t - off] : 0;
        __syncthreads();
        s[t] += v;
        __syncthreads();
    }
    if (t == 255) base = atomicAdd(&g_total, s[255]);
    __syncthreads();
    if (i < NN) {
        int start = base + s[t] - d;
        g_row_ptr[i] = start;
        g_row_end[i] = start + d;
        g_cursor[i]  = start;
        g_norm_dst[i] = rsqrtf(fmaxf((float)d, 1.f));
        g_norm_src[i] = rsqrtf(fmaxf((float)g_deg_out[i], 1.f));
    }
}

__global__ void fill_kernel(const int* __restrict__ src, const int* __restrict__ dst) {
    int i = blockIdx.x * 256 + threadIdx.x;
    if (i < NE) {
        int pos = atomicAdd(&g_cursor[dst[i]], 1);
        g_col[pos] = src[i];
    }
}

// ---------------------------------------------------------------------------
// h = V @ W_in + b_in ; g_hs16 = fp16(h * norm_src).  fp16 m16n8k16 mma.
__global__ void __launch_bounds__(256) input_gemm_tc(
        const float* __restrict__ V, const float* __restrict__ W,
        const float* __restrict__ b) {
    __shared__ __half Ws[DD * SWI];
    __shared__ __half As[64 * SWI];
    int tid = threadIdx.x;
    int node0 = blockIdx.x * 64;
    for (int q = tid; q < INV * DD / 4; q += 256) {
        int k = q >> 4, n4 = (q & 15) * 4;
        float4 w4 = ((const float4*)W)[q];
        Ws[(n4 + 0) * SWI + k] = __float2half_rn(w4.x);
        Ws[(n4 + 1) * SWI + k] = __float2half_rn(w4.y);
        Ws[(n4 + 2) * SWI + k] = __float2half_rn(w4.z);
        Ws[(n4 + 3) * SWI + k] = __float2half_rn(w4.w);
    }
    for (int q = tid; q < 64 * INV / 4; q += 256) {
        int row = q >> 5, c4 = (q & 31) * 4;
        int n = node0 + row;
        float4 a4 = (n < NN)
            ? *(const float4*)&V[(size_t)n * INV + c4]
            : make_float4(0.f, 0.f, 0.f, 0.f);
        __half2* p = (__half2*)&As[row * SWI + c4];
        p[0] = __floats2half2_rn(a4.x, a4.y);
        p[1] = __floats2half2_rn(a4.z, a4.w);
    }
    __syncthreads();
    int lane = tid & 31, warp = tid >> 5;
    int wr = warp & 3, wc = warp >> 2;
    int g = lane >> 2, tig = lane & 3;
    float c[4][4] = {};
#pragma unroll
    for (int kk = 0; kk < INV; kk += 16) {
        uint32_t a0 = *(const uint32_t*)&As[(wr * 16 + g) * SWI + kk + 2 * tig];
        uint32_t a1 = *(const uint32_t*)&As[(wr * 16 + g + 8) * SWI + kk + 2 * tig];
        uint32_t a2 = *(const uint32_t*)&As[(wr * 16 + g) * SWI + kk + 2 * tig + 8];
        uint32_t a3 = *(const uint32_t*)&As[(wr * 16 + g + 8) * SWI + kk + 2 * tig + 8];
#pragma unroll
        for (int nt = 0; nt < 4; nt++) {
            int nn = wc * 32 + nt * 8;
            uint32_t b0 = *(const uint32_t*)&Ws[(nn + g) * SWI + kk + 2 * tig];
            uint32_t b1 = *(const uint32_t*)&Ws[(nn + g) * SWI + kk + 2 * tig + 8];
            mma_f16(c[nt][0], c[nt][1], c[nt][2], c[nt][3],
                    a0, a1, a2, a3, b0, b1);
        }
    }
    int r1 = node0 + wr * 16 + g, r2 = r1 + 8;
    bool v1 = (r1 < NN), v2 = (r2 < NN);
    float ns1 = v1 ? g_norm_src[r1] : 0.f;
    float ns2 = v2 ? g_norm_src[r2] : 0.f;
#pragma unroll
    for (int nt = 0; nt < 4; nt++) {
        int f = wc * 32 + nt * 8 + tig * 2;
        float b0 = b[f], b1 = b[f + 1];
        if (v1) {
            float x = c[nt][0] + b0, y = c[nt][1] + b1;
            *(float2*)&g_h[(size_t)r1 * DD + f] = make_float2(x, y);
            *(__half2*)&g_hs16[(size_t)r1 * DD + f] = __floats2half2_rn(x * ns1, y * ns1);
        }
        if (v2) {
            float x = c[nt][2] + b0, y = c[nt][3] + b1;
            *(float2*)&g_h[(size_t)r2 * DD + f] = make_float2(x, y);
            *(__half2*)&g_hs16[(size_t)r2 * DD + f] = __floats2half2_rn(x * ns2, y * ns2);
        }
    }
}

// ---------------------------------------------------------------------------
// Persistent kernel: 4 x (gather -> gemm+stats -> bn_apply) + out, with
// soft grid barriers. All cross-phase global reads use __ldcg (L2-only).
struct GemmS {
    __half Ws[DD * SWH];
    __half As[64 * SWH];
    float ssum[DD], ssq[DD];
};
struct OutS {
    float Ws[DD * NC];
    float bs[NC];
    float sc[DD], sh[DD];
    float hrow[8][DD];
};
struct BnS { float sc[DD], sh[DD]; };

#define ACC4(r) do { const __half2* _hh = (const __half2*)&(r); float2 _t;   \
    _t = __half22float2(_hh[0]); ac0.x += _t.x; ac0.y += _t.y;               \
    _t = __half22float2(_hh[1]); ac1.x += _t.x; ac1.y += _t.y;               \
    _t = __half22float2(_hh[2]); ac2.x += _t.x; ac2.y += _t.y;               \
    _t = __half22float2(_hh[3]); ac3.x += _t.x; ac3.y += _t.y; } while (0)

__global__ void __launch_bounds__(256, 3) layers_kernel(
        const float* __restrict__ W_l, const float* __restrict__ b_l,
        const float* __restrict__ gamma, const float* __restrict__ beta,
        const float* __restrict__ W_out, const float* __restrict__ b_out,
        float* __restrict__ out) {
    __shared__ union { GemmS g; OutS o; BnS b; } S;
    int tid = threadIdx.x;
    int lane = tid & 31, warp = tid >> 5;
    unsigned phase = 0;

    for (int l = 0; l < NLAY; l++) {
        const float* Wl = W_l + (size_t)l * DD * DD;
        const float* bl = b_l + (size_t)l * DD;
        float* stats = g_stats + (size_t)l * 2 * DD;

        // ================= gather phase =================
        {
            int group = lane >> 3, sub = lane & 7;
            const float4* hs = (const float4*)g_hs16;
            const float4 z4 = make_float4(0.f, 0.f, 0.f, 0.f);
            for (int grp = blockIdx.x; grp < NN / 8; grp += GRID) {
                int node = grp * 8 + warp;
                int e0  = __ldg(&g_row_ptr[node]);
                int end = __ldg(&g_row_end[node]);
                float2 ac0 = {0.f, 0.f}, ac1 = {0.f, 0.f};
                float2 ac2 = {0.f, 0.f}, ac3 = {0.f, 0.f};
                for (int e = e0 + group; e < end; e += 16) {
                    int i1 = e + 4, i2 = e + 8, i3 = e + 12;
                    int s0 = __ldg(&g_col[e]);
                    int s1 = __ldg(&g_col[i1 < end ? i1 : e]);
                    int s2 = __ldg(&g_col[i2 < end ? i2 : e]);
                    int s3 = __ldg(&g_col[i3 < end ? i3 : e]);
                    float4 r0 = __ldcg(&hs[(size_t)s0 * 8 + sub]);
                    float4 r1 = __ldcg(&hs[(size_t)s1 * 8 + sub]);
                    float4 r2 = __ldcg(&hs[(size_t)s2 * 8 + sub]);
                    float4 r3 = __ldcg(&hs[(size_t)s3 * 8 + sub]);
                    if (i1 >= end) r1 = z4;
                    if (i2 >= end) r2 = z4;
                    if (i3 >= end) r3 = z4;
                    ACC4(r0); ACC4(r1); ACC4(r2); ACC4(r3);
                }
#pragma unroll
                for (int off = 8; off <= 16; off <<= 1) {
                    ac0.x += __shfl_xor_sync(0xffffffffu, ac0.x, off);
                    ac0.y += __shfl_xor_sync(0xffffffffu, ac0.y, off);
                    ac1.x += __shfl_xor_sync(0xffffffffu, ac1.x, off);
                    ac1.y += __shfl_xor_sync(0xffffffffu, ac1.y, off);
                    ac2.x += __shfl_xor_sync(0xffffffffu, ac2.x, off);
                    ac2.y += __shfl_xor_sync(0xffffffffu, ac2.y, off);
                    ac3.x += __shfl_xor_sync(0xffffffffu, ac3.x, off);
                    ac3.y += __shfl_xor_sync(0xffffffffu, ac3.y, off);
                }
                float nd = g_norm_dst[node];
                if (lane < 16) {
                    int half = lane >> 3;
                    __half2 o0, o1;
                    if (half == 0) {
                        o0 = __floats2half2_rn(ac0.x * nd, ac0.y * nd);
                        o1 = __floats2half2_rn(ac1.x * nd, ac1.y * nd);
                    } else {
                        o0 = __floats2half2_rn(ac2.x * nd, ac2.y * nd);
                        o1 = __floats2half2_rn(ac3.x * nd, ac3.y * nd);
                    }
                    __half2* op = (__half2*)&g_agg16[(size_t)node * DD + sub * 8 + half * 4];
                    op[0] = o0; op[1] = o1;
                }
            }
        }
        grid_bar(++phase * GRID);

        // ================= gemm + BN stats phase =================
        {
            // stage W transposed fp32 -> fp16 (once per layer)
            for (int q = tid; q < DD * DD / 4; q += 256) {
                int k = q >> 4, n4 = (q & 15) * 4;
                float4 w4 = ((const float4*)Wl)[q];
                S.g.Ws[(n4 + 0) * SWH + k] = __float2half_rn(w4.x);
                S.g.Ws[(n4 + 1) * SWH + k] = __float2half_rn(w4.y);
                S.g.Ws[(n4 + 2) * SWH + k] = __float2half_rn(w4.z);
                S.g.Ws[(n4 + 3) * SWH + k] = __float2half_rn(w4.w);
            }
            if (tid < DD) { S.g.ssum[tid] = 0.f; S.g.ssq[tid] = 0.f; }
            int wr = warp & 3, wc = warp >> 2;
            int g = lane >> 2, tig = lane & 3;
            for (int t = blockIdx.x; t < NTILE; t += GRID) {
                int node0 = t * 64;
                __syncthreads();
                for (int q = tid; q < 64 * DD / 8; q += 256) {
                    int row = q >> 3, c8 = (q & 7) * 8;
                    int n = node0 + row;
                    int4 v = (n < NN)
                        ? __ldcg((const int4*)&g_agg16[(size_t)n * DD + c8])
                        : make_int4(0, 0, 0, 0);
                    *(int4*)&S.g.As[row * SWH + c8] = v;
                }
                __syncthreads();
                float c[4][4] = {};
#pragma unroll
                for (int kk = 0; kk < DD; kk += 16) {
                    uint32_t a0 = *(const uint32_t*)&S.g.As[(wr * 16 + g) * SWH + kk + 2 * tig];
                    uint32_t a1 = *(const uint32_t*)&S.g.As[(wr * 16 + g + 8) * SWH + kk + 2 * tig];
                    uint32_t a2 = *(const uint32_t*)&S.g.As[(wr * 16 + g) * SWH + kk + 2 * tig + 8];
                    uint32_t a3 = *(const uint32_t*)&S.g.As[(wr * 16 + g + 8) * SWH + kk + 2 * tig + 8];
#pragma unroll
                    for (int nt = 0; nt < 4; nt++) {
                        int nn = wc * 32 + nt * 8;
                        uint32_t b0 = *(const uint32_t*)&S.g.Ws[(nn + g) * SWH + kk + 2 * tig];
                        uint32_t b1 = *(const uint32_t*)&S.g.Ws[(nn + g) * SWH + kk + 2 * tig + 8];
                        mma_f16(c[nt][0], c[nt][1], c[nt][2], c[nt][3],
                                a0, a1, a2, a3, b0, b1);
                    }
                }
                int r1 = node0 + wr * 16 + g, r2 = r1 + 8;
                bool v1 = (r1 < NN), v2 = (r2 < NN);
#pragma unroll
                for (int nt = 0; nt < 4; nt++) {
                    int f = wc * 32 + nt * 8 + tig * 2;
                    float b0 = bl[f], b1 = bl[f + 1];
                    float s0 = 0.f, s1 = 0.f, q0 = 0.f, q1 = 0.f;
                    if (v1) {
                        float x = c[nt][0] + b0, y = c[nt][1] + b1;
                        *(__half2*)&g_hc16[(size_t)r1 * DD + f] = __floats2half2_rn(x, y);
                        s0 += x; s1 += y; q0 += x * x; q1 += y * y;
                    }
                    if (v2) {
                        float x = c[nt][2] + b0, y = c[nt][3] + b1;
                        *(__half2*)&g_hc16[(size_t)r2 * DD + f] = __floats2half2_rn(x, y);
                        s0 += x; s1 += y; q0 += x * x; q1 += y * y;
                    }
#pragma unroll
                    for (int off = 4; off <= 16; off <<= 1) {
                        s0 += __shfl_xor_sync(0xffffffffu, s0, off);
                        s1 += __shfl_xor_sync(0xffffffffu, s1, off);
                        q0 += __shfl_xor_sync(0xffffffffu, q0, off);
                        q1 += __shfl_xor_sync(0xffffffffu, q1, off);
                    }
                    if (g == 0) {
                        atomicAdd(&S.g.ssum[f], s0);
                        atomicAdd(&S.g.ssum[f + 1], s1);
                        atomicAdd(&S.g.ssq[f], q0);
                        atomicAdd(&S.g.ssq[f + 1], q1);
                    }
                }
            }
            __syncthreads();
            if (tid < DD) {
                atomicAdd(&stats[tid],      S.g.ssum[tid]);
                atomicAdd(&stats[DD + tid], S.g.ssq[tid]);
            }
        }
        grid_bar(++phase * GRID);

        // ================= bn_apply phase (not last layer) =================
        if (l < NLAY - 1) {
            if (tid < DD) {
                float mean = __ldcg(&stats[tid]) * (1.f / NN);
                float ex2  = __ldcg(&stats[DD + tid]) * (1.f / NN);
                float inv  = rsqrtf(ex2 - mean * mean + 1e-5f);
                float s    = gamma[(size_t)l * DD + tid] * inv;
                S.b.sc[tid] = s;
                S.b.sh[tid] = beta[(size_t)l * DD + tid] - mean * s;
            }
            __syncthreads();
            for (int ch = blockIdx.x; ch < NN * 16 / 256; ch += GRID) {
                int i = ch * 256 + tid;
                int n = i >> 4;
                int f0 = (i & 15) * 4;
                const __half2* cp = (const __half2*)&g_hc16[(size_t)i * 4];
                float2 c01 = __half22float2(__ldcg(&cp[0]));
                float2 c23 = __half22float2(__ldcg(&cp[1]));
                float4 h4 = __ldcg(&((const float4*)g_h)[i]);
                float ns = g_norm_src[n];
                float v;
                v = c01.x * S.b.sc[f0 + 0] + S.b.sh[f0 + 0]; h4.x += (v >= 0.f) ? v : 0.2f * v;
                v = c01.y * S.b.sc[f0 + 1] + S.b.sh[f0 + 1]; h4.y += (v >= 0.f) ? v : 0.2f * v;
                v = c23.x * S.b.sc[f0 + 2] + S.b.sh[f0 + 2]; h4.z += (v >= 0.f) ? v : 0.2f * v;
                v = c23.y * S.b.sc[f0 + 3] + S.b.sh[f0 + 3]; h4.w += (v >= 0.f) ? v : 0.2f * v;
                ((float4*)g_h)[i] = h4;
                __half2* hp = (__half2*)&g_hs16[(size_t)i * 4];
                hp[0] = __floats2half2_rn(h4.x * ns, h4.y * ns);
                hp[1] = __floats2half2_rn(h4.z * ns, h4.w * ns);
            }
            grid_bar(++phase * GRID);
        }
    }

    // ================= out phase: BN(l3) + residual + logits + log_softmax ==
    {
        const float* stats = g_stats + (size_t)(NLAY - 1) * 2 * DD;
        for (int i = tid; i < DD * NC; i += 256) S.o.Ws[i] = W_out[i];
        if (tid < NC) S.o.bs[tid] = b_out[tid];
        if (tid < DD) {
            float mean = __ldcg(&stats[tid]) * (1.f / NN);
            float ex2  = __ldcg(&stats[DD + tid]) * (1.f / NN);
            float inv  = rsqrtf(ex2 - mean * mean + 1e-5f);
            float s    = gamma[(size_t)(NLAY - 1) * DD + tid] * inv;
            S.o.sc[tid] = s;
            S.o.sh[tid] = beta[(size_t)(NLAY - 1) * DD + tid] - mean * s;
        }
        __syncthreads();
        for (int grp = blockIdx.x; grp < NN / 8; grp += GRID) {
            int n = grp * 8 + warp;
            {
                int f = lane * 2;
                float2 c  = __half22float2(__ldcg((const __half2*)&g_hc16[(size_t)n * DD + f]));
                float2 h2;
                {
                    float2 t2 = *(const float2*)&g_h[(size_t)n * DD + f];
                    // g_h written by bn phase of l2 (same kernel) -> use ldcg
                    h2.x = __ldcg(&g_h[(size_t)n * DD + f]);
                    h2.y = __ldcg(&g_h[(size_t)n * DD + f + 1]);
                    (void)t2;
                }
                float v;
                v = c.x * S.o.sc[f]     + S.o.sh[f];     h2.x += (v >= 0.f) ? v : 0.2f * v;
                v = c.y * S.o.sc[f + 1] + S.o.sh[f + 1]; h2.y += (v >= 0.f) ? v : 0.2f * v;
                S.o.hrow[warp][f]     = h2.x;
                S.o.hrow[warp][f + 1] = h2.y;
            }
            __syncwarp();
            int c0 = lane, c1 = lane + 32;
            bool has1 = (c1 < NC);
            float acc0 = S.o.bs[c0];
            float acc1 = has1 ? S.o.bs[c1] : 0.f;
#pragma unroll
            for (int k = 0; k < DD; k++) {
                float hv = S.o.hrow[warp][k];
                acc0 += hv * S.o.Ws[k * NC + c0];
                if (has1) acc1 += hv * S.o.Ws[k * NC + c1];
            }
            float m = has1 ? fmaxf(acc0, acc1) : acc0;
#pragma unroll
            for (int off = 16; off; off >>= 1)
                m = fmaxf(m, __shfl_xor_sync(0xffffffffu, m, off));
            float e = expf(acc0 - m) + (has1 ? expf(acc1 - m) : 0.f);
#pragma unroll
            for (int off = 16; off; off >>= 1)
                e += __shfl_xor_sync(0xffffffffu, e, off);
            float ls = m + logf(e);
            out[(size_t)n * NC + c0] = acc0 - ls;
            if (has1) out[(size_t)n * NC + c1] = acc1 - ls;
            __syncwarp();
        }
    }
}

// ---------------------------------------------------------------------------
extern "C" void kernel_launch(void* const* d_in, const int* in_sizes, int n_in,
                              void* d_out, int out_size) {
    const float* V     = (const float*)d_in[0];
    const int*   src   = (const int*)d_in[1];
    const int*   dst   = (const int*)d_in[2];
    const float* W_in  = (const float*)d_in[3];
    const float* b_in  = (const float*)d_in[4];
    const float* W_l   = (const float*)d_in[5];
    const float* b_l   = (const float*)d_in[6];
    const float* gamma = (const float*)d_in[7];
    const float* beta  = (const float*)d_in[8];
    const float* W_out = (const float*)d_in[9];
    const float* b_out = (const float*)d_in[10];
    float* out = (float*)d_out;

    init_kernel<<<NSB, 256>>>();
    deg_kernel<<<(NE + 255) / 256, 256>>>(src, dst);
    offsets_kernel<<<NSB, 256>>>();
    fill_kernel<<<(NE + 255) / 256, 256>>>(src, dst);
    input_gemm_tc<<<(NN + 63) / 64, 256>>>(V, W_in, b_in);
    layers_kernel<<<GRID, 256>>>(W_l, b_l, gamma, beta, W_out, b_out, out);
}

// round 13
// speedup vs baseline: 1.1383x; 1.1383x over previous
#include <cuda_runtime.h>
#include <cuda_fp16.h>
#include <cstdint>

#define NN   100000
#define DD   64
#define INV  128
#define NC   40
#define NE   1600000
#define NLAY 4
#define NSB  391         // offset blocks: ceil(NN/256)
#define SWH  72          // smem stride in halves (144B = 4 banks mod 32)
#define SWI  136         // input gemm stride in halves (272B = 4 banks mod 32)
#define NTILE 1563       // ceil(NN/64)

// ---- scratch (device globals: no allocations allowed) ----
__device__ __align__(128) float  g_h[NN * DD];
__device__ __align__(128) __half g_hs16[NN * DD];   // (h * norm_src) in fp16
__device__ __align__(128) __half g_agg16[NN * DD];  // gathered agg in fp16
__device__ __align__(128) __half g_hc16[NN * DD];   // conv output in fp16
__device__ float g_norm_src[NN];
__device__ float g_norm_dst[NN];
__device__ int   g_deg_out[NN];   // out-degree counts (zeroed by offsets)
__device__ int   g_cnt[NN];       // in-degree counts  (zeroed by offsets)
__device__ int   g_row_ptr[NN];
__device__ int   g_row_end[NN];
__device__ int   g_cursor[NN];    // fully overwritten by offsets each call
__device__ int   g_col[NE];
__device__ int   g_total;         // reset by last offsets block
__device__ int   g_done;          // reset by last offsets block
__device__ float g_stats[NLAY * 2 * DD];  // slot l zeroed by gather(l) block 0

// ---------------------------------------------------------------------------
__device__ __forceinline__ void mma_f16(
        float& c0, float& c1, float& c2, float& c3,
        uint32_t a0, uint32_t a1, uint32_t a2, uint32_t a3,
        uint32_t b0, uint32_t b1) {
    asm volatile(
        "mma.sync.aligned.m16n8k16.row.col.f32.f16.f16.f32 "
        "{%0,%1,%2,%3}, {%4,%5,%6,%7}, {%8,%9}, {%0,%1,%2,%3};"
        : "+f"(c0), "+f"(c1), "+f"(c2), "+f"(c3)
        : "r"(a0), "r"(a1), "r"(a2), "r"(a3), "r"(b0), "r"(b1));
}

// ---------------------------------------------------------------------------
__global__ void deg_kernel(const int* __restrict__ src, const int* __restrict__ dst) {
    int i = blockIdx.x * 256 + threadIdx.x;
    if (i < NE) {
        atomicAdd(&g_deg_out[src[i]], 1);
        atomicAdd(&g_cnt[dst[i]], 1);
    }
}

// Single-pass offset allocation: block-local scan + one atomicAdd per block.
// Also restores all prologue counters to zero for the next graph replay.
__global__ void offsets_kernel() {
    __shared__ int s[256];
    __shared__ int base;
    int t = threadIdx.x;
    int i = blockIdx.x * 256 + t;
    int d = 0, dout = 0;
    if (i < NN) {
        d    = g_cnt[i];      g_cnt[i] = 0;        // self-restore for replay
        dout = g_deg_out[i];  g_deg_out[i] = 0;    // self-restore for replay
    }
    s[t] = d;
    __syncthreads();
    for (int off = 1; off < 256; off <<= 1) {
        int v = (t >= off) ? s[t - off] : 0;
        __syncthreads();
        s[t] += v;
        __syncthreads();
    }
    if (t == 255) {
        base = atomicAdd(&g_total, s[255]);
        if (atomicAdd(&g_done, 1) == NSB - 1) {    // last block resets counters
            g_total = 0;
            g_done = 0;
        }
    }
    __syncthreads();
    if (i < NN) {
        int start = base + s[t] - d;
        g_row_ptr[i] = start;
        g_row_end[i] = start + d;
        g_cursor[i]  = start;
        g_norm_dst[i] = rsqrtf(fmaxf((float)d, 1.f));
        g_norm_src[i] = rsqrtf(fmaxf((float)dout, 1.f));
    }
}

__global__ void fill_kernel(const int* __restrict__ src, const int* __restrict__ dst) {
    int i = blockIdx.x * 256 + threadIdx.x;
    if (i < NE) {
        int pos = atomicAdd(&g_cursor[dst[i]], 1);
        g_col[pos] = src[i];
    }
}

// ---------------------------------------------------------------------------
// h = V @ W_in + b_in ; g_hs16 = fp16(h * norm_src).  fp16 m16n8k16 mma.
// 2 node-tiles per block (W staged once).
__global__ void __launch_bounds__(256) input_gemm_tc(
        const float* __restrict__ V, const float* __restrict__ W,
        const float* __restrict__ b) {
    __shared__ __half Ws[DD * SWI];
    __shared__ __half As[64 * SWI];
    int tid = threadIdx.x;
    // stage W transposed: W[k][n] fp32 -> Wt[n][k] fp16 (once per block)
    for (int q = tid; q < INV * DD / 4; q += 256) {
        int k = q >> 4, n4 = (q & 15) * 4;
        float4 w4 = ((const float4*)W)[q];
        Ws[(n4 + 0) * SWI + k] = __float2half_rn(w4.x);
        Ws[(n4 + 1) * SWI + k] = __float2half_rn(w4.y);
        Ws[(n4 + 2) * SWI + k] = __float2half_rn(w4.z);
        Ws[(n4 + 3) * SWI + k] = __float2half_rn(w4.w);
    }
    int lane = tid & 31, warp = tid >> 5;
    int wr = warp & 3, wc = warp >> 2;
    int g = lane >> 2, tig = lane & 3;
#pragma unroll 1
    for (int t2 = 0; t2 < 2; t2++) {
        int tile = blockIdx.x * 2 + t2;
        if (tile >= NTILE) break;
        int node0 = tile * 64;
        __syncthreads();
        for (int q = tid; q < 64 * INV / 4; q += 256) {
            int row = q >> 5, c4 = (q & 31) * 4;
            int n = node0 + row;
            float4 a4 = (n < NN)
                ? *(const float4*)&V[(size_t)n * INV + c4]
                : make_float4(0.f, 0.f, 0.f, 0.f);
            __half2* p = (__half2*)&As[row * SWI + c4];
            p[0] = __floats2half2_rn(a4.x, a4.y);
            p[1] = __floats2half2_rn(a4.z, a4.w);
        }
        __syncthreads();
        float c[4][4] = {};
#pragma unroll
        for (int kk = 0; kk < INV; kk += 16) {
            uint32_t a0 = *(const uint32_t*)&As[(wr * 16 + g) * SWI + kk + 2 * tig];
            uint32_t a1 = *(const uint32_t*)&As[(wr * 16 + g + 8) * SWI + kk + 2 * tig];
            uint32_t a2 = *(const uint32_t*)&As[(wr * 16 + g) * SWI + kk + 2 * tig + 8];
            uint32_t a3 = *(const uint32_t*)&As[(wr * 16 + g + 8) * SWI + kk + 2 * tig + 8];
#pragma unroll
            for (int nt = 0; nt < 4; nt++) {
                int nn = wc * 32 + nt * 8;
                uint32_t b0 = *(const uint32_t*)&Ws[(nn + g) * SWI + kk + 2 * tig];
                uint32_t b1 = *(const uint32_t*)&Ws[(nn + g) * SWI + kk + 2 * tig + 8];
                mma_f16(c[nt][0], c[nt][1], c[nt][2], c[nt][3],
                        a0, a1, a2, a3, b0, b1);
            }
        }
        int r1 = node0 + wr * 16 + g, r2 = r1 + 8;
        bool v1 = (r1 < NN), v2 = (r2 < NN);
        float ns1 = v1 ? g_norm_src[r1] : 0.f;
        float ns2 = v2 ? g_norm_src[r2] : 0.f;
#pragma unroll
        for (int nt = 0; nt < 4; nt++) {
            int f = wc * 32 + nt * 8 + tig * 2;
            float b0 = b[f], b1 = b[f + 1];
            if (v1) {
                float x = c[nt][0] + b0, y = c[nt][1] + b1;
                *(float2*)&g_h[(size_t)r1 * DD + f] = make_float2(x, y);
                *(__half2*)&g_hs16[(size_t)r1 * DD + f] = __floats2half2_rn(x * ns1, y * ns1);
            }
            if (v2) {
                float x = c[nt][2] + b0, y = c[nt][3] + b1;
                *(float2*)&g_h[(size_t)r2 * DD + f] = make_float2(x, y);
                *(__half2*)&g_hs16[(size_t)r2 * DD + f] = __floats2half2_rn(x * ns2, y * ns2);
            }
        }
    }
}

// ---------------------------------------------------------------------------
// CSR gather segment-sum, fp16 rows, LDG.128, masked MLP-4 (near BW floor).
// Block 0 also zeroes this layer's BN stats slot (gemm runs strictly after).
#define ACC4(r) do { const __half2* _hh = (const __half2*)&(r); float2 _t;   \
    _t = __half22float2(_hh[0]); ac0.x += _t.x; ac0.y += _t.y;               \
    _t = __half22float2(_hh[1]); ac1.x += _t.x; ac1.y += _t.y;               \
    _t = __half22float2(_hh[2]); ac2.x += _t.x; ac2.y += _t.y;               \
    _t = __half22float2(_hh[3]); ac3.x += _t.x; ac3.y += _t.y; } while (0)

__global__ void __launch_bounds__(256) gather_kernel(float* __restrict__ stats) {
    int tid = threadIdx.x;
    if (blockIdx.x == 0 && tid < 2 * DD) stats[tid] = 0.f;
    int lane = tid & 31;
    int node = blockIdx.x * 8 + (tid >> 5);       // NN divisible by 8
    int group = lane >> 3;                         // 0..3
    int sub   = lane & 7;                          // 0..7
    int e0  = __ldg(&g_row_ptr[node]);
    int end = __ldg(&g_row_end[node]);
    const float4* __restrict__ hs = (const float4*)g_hs16;
    const float4 z4 = make_float4(0.f, 0.f, 0.f, 0.f);

    float2 ac0 = {0.f, 0.f}, ac1 = {0.f, 0.f}, ac2 = {0.f, 0.f}, ac3 = {0.f, 0.f};
    for (int e = e0 + group; e < end; e += 16) {
        int i1 = e + 4, i2 = e + 8, i3 = e + 12;
        int s0 = __ldg(&g_col[e]);
        int s1 = __ldg(&g_col[i1 < end ? i1 : e]);
        int s2 = __ldg(&g_col[i2 < end ? i2 : e]);
        int s3 = __ldg(&g_col[i3 < end ? i3 : e]);
        float4 r0 = hs[(size_t)s0 * 8 + sub];
        float4 r1 = hs[(size_t)s1 * 8 + sub];
        float4 r2 = hs[(size_t)s2 * 8 + sub];
        float4 r3 = hs[(size_t)s3 * 8 + sub];
        if (i1 >= end) r1 = z4;
        if (i2 >= end) r2 = z4;
        if (i3 >= end) r3 = z4;
        ACC4(r0); ACC4(r1); ACC4(r2); ACC4(r3);
    }
#pragma unroll
    for (int off = 8; off <= 16; off <<= 1) {
        ac0.x += __shfl_xor_sync(0xffffffffu, ac0.x, off);
        ac0.y += __shfl_xor_sync(0xffffffffu, ac0.y, off);
        ac1.x += __shfl_xor_sync(0xffffffffu, ac1.x, off);
        ac1.y += __shfl_xor_sync(0xffffffffu, ac1.y, off);
        ac2.x += __shfl_xor_sync(0xffffffffu, ac2.x, off);
        ac2.y += __shfl_xor_sync(0xffffffffu, ac2.y, off);
        ac3.x += __shfl_xor_sync(0xffffffffu, ac3.x, off);
        ac3.y += __shfl_xor_sync(0xffffffffu, ac3.y, off);
    }
    float nd = g_norm_dst[node];
    if (lane < 16) {
        int half = lane >> 3;
        __half2 o0, o1;
        if (half == 0) {
            o0 = __floats2half2_rn(ac0.x * nd, ac0.y * nd);
            o1 = __floats2half2_rn(ac1.x * nd, ac1.y * nd);
        } else {
            o0 = __floats2half2_rn(ac2.x * nd, ac2.y * nd);
            o1 = __floats2half2_rn(ac3.x * nd, ac3.y * nd);
        }
        __half2* op = (__half2*)&g_agg16[(size_t)node * DD + sub * 8 + half * 4];
        op[0] = o0; op[1] = o1;
    }
}

// ---------------------------------------------------------------------------
// hc16 = fp16(agg @ W + b) via fp16 mma; BN stats into stats slot.
// 2 node-tiles per block (W staged once).
__global__ void __launch_bounds__(256) gemm_bn_tc(
        const float* __restrict__ W, const float* __restrict__ bias,
        float* __restrict__ stats) {
    __shared__ __half Ws[DD * SWH];
    __shared__ __half As[64 * SWH];
    __shared__ float ssum[DD], ssq[DD];
    int tid = threadIdx.x;
    if (tid < DD) { ssum[tid] = 0.f; ssq[tid] = 0.f; }
    for (int q = tid; q < DD * DD / 4; q += 256) {
        int k = q >> 4, n4 = (q & 15) * 4;
        float4 w4 = ((const float4*)W)[q];
        Ws[(n4 + 0) * SWH + k] = __float2half_rn(w4.x);
        Ws[(n4 + 1) * SWH + k] = __float2half_rn(w4.y);
        Ws[(n4 + 2) * SWH + k] = __float2half_rn(w4.z);
        Ws[(n4 + 3) * SWH + k] = __float2half_rn(w4.w);
    }
    int lane = tid & 31, warp = tid >> 5;
    int wr = warp & 3, wc = warp >> 2;
    int g = lane >> 2, tig = lane & 3;
#pragma unroll 1
    for (int t2 = 0; t2 < 2; t2++) {
        int tile = blockIdx.x * 2 + t2;
        if (tile >= NTILE) break;
        int node0 = tile * 64;
        __syncthreads();
        for (int q = tid; q < 64 * DD / 8; q += 256) {
            int row = q >> 3, c8 = (q & 7) * 8;
            int n = node0 + row;
            int4 v = (n < NN)
                ? *(const int4*)&g_agg16[(size_t)n * DD + c8]
                : make_int4(0, 0, 0, 0);
            *(int4*)&As[row * SWH + c8] = v;
        }
        __syncthreads();
        float c[4][4] = {};
#pragma unroll
        for (int kk = 0; kk < DD; kk += 16) {
            uint32_t a0 = *(const uint32_t*)&As[(wr * 16 + g) * SWH + kk + 2 * tig];
            uint32_t a1 = *(const uint32_t*)&As[(wr * 16 + g + 8) * SWH + kk + 2 * tig];
            uint32_t a2 = *(const uint32_t*)&As[(wr * 16 + g) * SWH + kk + 2 * tig + 8];
            uint32_t a3 = *(const uint32_t*)&As[(wr * 16 + g + 8) * SWH + kk + 2 * tig + 8];
#pragma unroll
            for (int nt = 0; nt < 4; nt++) {
                int nn = wc * 32 + nt * 8;
                uint32_t b0 = *(const uint32_t*)&Ws[(nn + g) * SWH + kk + 2 * tig];
                uint32_t b1 = *(const uint32_t*)&Ws[(nn + g) * SWH + kk + 2 * tig + 8];
                mma_f16(c[nt][0], c[nt][1], c[nt][2], c[nt][3],
                        a0, a1, a2, a3, b0, b1);
            }
        }
        int r1 = node0 + wr * 16 + g, r2 = r1 + 8;
        bool v1 = (r1 < NN), v2 = (r2 < NN);
#pragma unroll
        for (int nt = 0; nt < 4; nt++) {
            int f = wc * 32 + nt * 8 + tig * 2;
            float b0 = bias[f], b1 = bias[f + 1];
            float s0 = 0.f, s1 = 0.f, q0 = 0.f, q1 = 0.f;
            if (v1) {
                float x = c[nt][0] + b0, y = c[nt][1] + b1;
                *(__half2*)&g_hc16[(size_t)r1 * DD + f] = __floats2half2_rn(x, y);
                s0 += x; s1 += y; q0 += x * x; q1 += y * y;
            }
            if (v2) {
                float x = c[nt][2] + b0, y = c[nt][3] + b1;
                *(__half2*)&g_hc16[(size_t)r2 * DD + f] = __floats2half2_rn(x, y);
                s0 += x; s1 += y; q0 += x * x; q1 += y * y;
            }
#pragma unroll
            for (int off = 4; off <= 16; off <<= 1) {
                s0 += __shfl_xor_sync(0xffffffffu, s0, off);
                s1 += __shfl_xor_sync(0xffffffffu, s1, off);
                q0 += __shfl_xor_sync(0xffffffffu, q0, off);
                q1 += __shfl_xor_sync(0xffffffffu, q1, off);
            }
            if (g == 0) {
                atomicAdd(&ssum[f], s0);     atomicAdd(&ssum[f + 1], s1);
                atomicAdd(&ssq[f], q0);      atomicAdd(&ssq[f + 1], q1);
            }
        }
    }
    __syncthreads();
    if (tid < DD) {
        atomicAdd(&stats[tid],      ssum[tid]);
        atomicAdd(&stats[DD + tid], ssq[tid]);
    }
}

// ---------------------------------------------------------------------------
// BN finalize + apply + leakyrelu + residual; write g_hs16 for next layer.
// 2 chunks per thread for ILP.
__global__ void bn_apply_kernel(const float* __restrict__ gamma,
                                const float* __restrict__ beta,
                                const float* __restrict__ stats) {
    __shared__ float sc[DD], sh[DD];
    int tid = threadIdx.x;
    if (tid < DD) {
        float mean = stats[tid] * (1.f / NN);
        float ex2  = stats[DD + tid] * (1.f / NN);
        float inv  = rsqrtf(ex2 - mean * mean + 1e-5f);
        float s    = gamma[tid] * inv;
        sc[tid] = s;
        sh[tid] = beta[tid] - mean * s;
    }
    __syncthreads();
#pragma unroll
    for (int u = 0; u < 2; u++) {
        int i = blockIdx.x * 512 + u * 256 + tid;   // over NN*16 float4s
        if (i >= NN * (DD / 4)) return;
        int n = i >> 4;
        int f0 = (i & 15) * 4;
        const __half2* cp = (const __half2*)&g_hc16[(size_t)i * 4];
        float2 c01 = __half22float2(cp[0]);
        float2 c23 = __half22float2(cp[1]);
        float4 h4 = ((const float4*)g_h)[i];
        float ns = g_norm_src[n];
        float v;
        v = c01.x * sc[f0 + 0] + sh[f0 + 0]; h4.x += (v >= 0.f) ? v : 0.2f * v;
        v = c01.y * sc[f0 + 1] + sh[f0 + 1]; h4.y += (v >= 0.f) ? v : 0.2f * v;
        v = c23.x * sc[f0 + 2] + sh[f0 + 2]; h4.z += (v >= 0.f) ? v : 0.2f * v;
        v = c23.y * sc[f0 + 3] + sh[f0 + 3]; h4.w += (v >= 0.f) ? v : 0.2f * v;
        ((float4*)g_h)[i] = h4;
        __half2* hp = (__half2*)&g_hs16[(size_t)i * 4];
        hp[0] = __floats2half2_rn(h4.x * ns, h4.y * ns);
        hp[1] = __floats2half2_rn(h4.z * ns, h4.w * ns);
    }
}

// ---------------------------------------------------------------------------
// Final fused kernel: BN(l=3)+leaky+residual, logits + log_softmax.
__global__ void __launch_bounds__(256) out_kernel(
        const float* __restrict__ gamma, const float* __restrict__ beta,
        const float* __restrict__ stats,
        const float* __restrict__ W, const float* __restrict__ b,
        float* __restrict__ out) {
    __shared__ float Ws[DD * NC];   // 10 KB
    __shared__ float bs[NC];
    __shared__ float sc[DD], sh[DD];
    __shared__ float hrow[8][DD];
    int tid = threadIdx.x;          // 256 threads = 8 warps
    for (int i = tid; i < DD * NC; i += 256) Ws[i] = W[i];
    if (tid < NC) bs[tid] = b[tid];
    if (tid < DD) {
        float mean = stats[tid] * (1.f / NN);
        float ex2  = stats[DD + tid] * (1.f / NN);
        float inv  = rsqrtf(ex2 - mean * mean + 1e-5f);
        float s    = gamma[tid] * inv;
        sc[tid] = s;
        sh[tid] = beta[tid] - mean * s;
    }
    __syncthreads();
    int warp = tid >> 5, lane = tid & 31;
    int n = blockIdx.x * 8 + warp;  // NN divisible by 8
    if (n >= NN) return;
    {
        int f = lane * 2;
        float2 c  = __half22float2(*(const __half2*)&g_hc16[(size_t)n * DD + f]);
        float2 h2 = *(const float2*)&g_h[(size_t)n * DD + f];
        float v;
        v = c.x * sc[f]     + sh[f];     h2.x += (v >= 0.f) ? v : 0.2f * v;
        v = c.y * sc[f + 1] + sh[f + 1]; h2.y += (v >= 0.f) ? v : 0.2f * v;
        hrow[warp][f]     = h2.x;
        hrow[warp][f + 1] = h2.y;
    }
    __syncwarp();
    int c0 = lane, c1 = lane + 32;
    bool has1 = (c1 < NC);
    float acc0 = bs[c0];
    float acc1 = has1 ? bs[c1] : 0.f;
#pragma unroll
    for (int k = 0; k < DD; k++) {
        float hv = hrow[warp][k];
        acc0 += hv * Ws[k * NC + c0];
        if (has1) acc1 += hv * Ws[k * NC + c1];
    }
    float m = has1 ? fmaxf(acc0, acc1) : acc0;
#pragma unroll
    for (int off = 16; off; off >>= 1) m = fmaxf(m, __shfl_xor_sync(0xffffffffu, m, off));
    float e = expf(acc0 - m) + (has1 ? expf(acc1 - m) : 0.f);
#pragma unroll
    for (int off = 16; off; off >>= 1) e += __shfl_xor_sync(0xffffffffu, e, off);
    float ls = m + logf(e);
    out[(size_t)n * NC + c0] = acc0 - ls;
    if (has1) out[(size_t)n * NC + c1] = acc1 - ls;
}

// ---------------------------------------------------------------------------
extern "C" void kernel_launch(void* const* d_in, const int* in_sizes, int n_in,
                              void* d_out, int out_size) {
    const float* V     = (const float*)d_in[0];
    const int*   src   = (const int*)d_in[1];
    const int*   dst   = (const int*)d_in[2];
    const float* W_in  = (const float*)d_in[3];
    const float* b_in  = (const float*)d_in[4];
    const float* W_l   = (const float*)d_in[5];
    const float* b_l   = (const float*)d_in[6];
    const float* gamma = (const float*)d_in[7];
    const float* beta  = (const float*)d_in[8];
    const float* W_out = (const float*)d_in[9];
    const float* b_out = (const float*)d_in[10];
    float* out = (float*)d_out;

    float* stats_base;
    cudaGetSymbolAddress((void**)&stats_base, g_stats);

    deg_kernel<<<(NE + 255) / 256, 256>>>(src, dst);
    offsets_kernel<<<NSB, 256>>>();
    fill_kernel<<<(NE + 255) / 256, 256>>>(src, dst);

    input_gemm_tc<<<(NTILE + 1) / 2, 256>>>(V, W_in, b_in);

    for (int l = 0; l < NLAY; l++) {
        float* stats = stats_base + (size_t)l * 2 * DD;
        gather_kernel<<<NN / 8, 256>>>(stats);
        gemm_bn_tc<<<(NTILE + 1) / 2, 256>>>(W_l + (size_t)l * DD * DD,
                                             b_l + (size_t)l * DD, stats);
        if (l < NLAY - 1) {
            bn_apply_kernel<<<(NN * (DD / 4) + 511) / 512, 256>>>(
                gamma + (size_t)l * DD, beta + (size_t)l * DD, stats);
        }
    }

    out_kernel<<<NN / 8, 256>>>(gamma + (size_t)(NLAY - 1) * DD,
                                beta + (size_t)(NLAY - 1) * DD,
                                stats_base + (size_t)(NLAY - 1) * 2 * DD,
                                W_out, b_out, out);
}